// round 1
// baseline (speedup 1.0000x reference)
#include <cuda_runtime.h>
#include <cstdint>

#define HD   128
#define RR   8
#define NMAX 50000
#define KTOT (HD + RR * HD)   // 1152

// ---------------- scratch (static device globals; no allocation) ----------------
__device__ float g_agg[(size_t)NMAX * RR * HD];   // [N, 8, 128] relation-wise sums
__device__ int   g_cnt[NMAX * RR];                // [N, 8] in-degree per relation
__device__ float g_h1[(size_t)NMAX * HD];
__device__ float g_h2[(size_t)NMAX * HD];

// ---------------- packed f32x2 helpers (2x FFMA throughput vs 3-reg FFMA) -------
__device__ __forceinline__ unsigned long long bcast2(float x) {
    unsigned long long r;
    unsigned u = __float_as_uint(x);
    asm("mov.b64 %0, {%1, %1};" : "=l"(r) : "r"(u));
    return r;
}
__device__ __forceinline__ void ffma2(unsigned long long& d,
                                      unsigned long long a, unsigned long long b) {
    asm("fma.rn.f32x2 %0, %1, %2, %0;" : "+l"(d) : "l"(a), "l"(b));
}
__device__ __forceinline__ float2 unpack2(unsigned long long v) {
    float2 f;
    asm("mov.b64 {%0, %1}, %2;" : "=f"(f.x), "=f"(f.y) : "l"(v));
    return f;
}

// ---------------- kernels ----------------

__global__ void zero_kernel(float4* agg, int* cnt, long n4, int ncnt, int do_cnt) {
    long i = blockIdx.x * (long)blockDim.x + threadIdx.x;
    long stride = (long)gridDim.x * blockDim.x;
    float4 z = make_float4(0.f, 0.f, 0.f, 0.f);
    for (long k = i; k < n4; k += stride) agg[k] = z;
    if (do_cnt)
        for (long k = i; k < ncnt; k += stride) cnt[k] = 0;
}

__global__ void count_kernel(const int* __restrict__ dst, const int* __restrict__ et,
                             int* cnt, int E) {
    int e = blockIdx.x * blockDim.x + threadIdx.x;
    if (e < E) atomicAdd(&cnt[dst[e] * RR + et[e]], 1);
}

// One warp per edge: 32 lanes x float4 = 128 floats. Gather x[src] (L2-resident),
// vector-reduce into agg[dst, etype, :].
__global__ void scatter_kernel(const float* __restrict__ feat,
                               const int* __restrict__ src, const int* __restrict__ dst,
                               const int* __restrict__ et, float* agg, int E) {
    int t = blockIdx.x * blockDim.x + threadIdx.x;
    int e = t >> 5, lane = t & 31;
    if (e >= E) return;
    int s = src[e], d = dst[e], r = et[e];
    float4 v = *(const float4*)(feat + (size_t)s * HD + lane * 4);
    float* a = agg + (size_t)d * (RR * HD) + r * HD + lane * 4;
    asm volatile("red.global.add.v4.f32 [%0], {%1, %2, %3, %4};"
                 :: "l"(a), "f"(v.x), "f"(v.y), "f"(v.z), "f"(v.w) : "memory");
}

// C[M,128] = relu( [X | invcnt*agg] @ [root ; W] + bias )
// 128x128 tile per CTA, BK=16, 256 threads, 8x8 micro-tile per thread, f32x2 FMAs.
__global__ __launch_bounds__(256, 2) void rgcn_gemm(
    const float* __restrict__ X, const float* __restrict__ agg,
    const int* __restrict__ cnt,
    const float* __restrict__ root, const float* __restrict__ W,
    const float* __restrict__ bias, float* __restrict__ out, int M) {

    __shared__ float As[16][132];       // transposed: As[k][row]
    __shared__ float Bs[16][132];       // Bs[k][col]
    __shared__ float InvS[128][RR];

    int tid = threadIdx.x;
    int brow = blockIdx.x * 128;

    // per-(row, relation) 1/max(cnt,1)
    for (int i = tid; i < 128 * RR; i += 256) {
        int r = i >> 3, rel = i & 7;
        int g = brow + r;
        int c = (g < M) ? cnt[g * RR + rel] : 1;
        InvS[r][rel] = 1.0f / (float)(c > 1 ? c : 1);
    }

    unsigned long long acc[8][4];
#pragma unroll
    for (int i = 0; i < 8; i++)
#pragma unroll
        for (int j = 0; j < 4; j++) acc[i][j] = 0ull;

    int ty = tid >> 4, tx = tid & 15;
    int row0 = ty * 8, col0 = tx * 8;

    __syncthreads();   // InvS ready

    for (int k0 = 0; k0 < KTOT; k0 += 16) {
        bool isX = (k0 < HD);
        const float* Ab = isX ? (X + k0) : (agg + (k0 - HD));
        int astr = isX ? HD : (RR * HD);
        int rel = isX ? 0 : ((k0 - HD) >> 7);
        const float* Bb = isX ? (root + (size_t)k0 * HD) : (W + (size_t)(k0 - HD) * HD);

        // load A tile 128x16 (transposed into smem, scaled by inv-count)
#pragma unroll
        for (int p = 0; p < 2; p++) {
            int idx = tid + p * 256;        // 0..511
            int r = idx >> 2;               // row 0..127
            int c4 = (idx & 3) * 4;         // col 0,4,8,12
            int g = brow + r;
            float4 v = make_float4(0.f, 0.f, 0.f, 0.f);
            if (g < M) v = *(const float4*)(Ab + (size_t)g * astr + c4);
            float s = isX ? 1.0f : InvS[r][rel];
            As[c4 + 0][r] = v.x * s;
            As[c4 + 1][r] = v.y * s;
            As[c4 + 2][r] = v.z * s;
            As[c4 + 3][r] = v.w * s;
        }
        // load B tile 16x128
#pragma unroll
        for (int p = 0; p < 2; p++) {
            int idx = tid + p * 256;
            int kk = idx >> 5;              // 0..15
            int c4 = (idx & 31) * 4;        // 0..124
            *(float4*)&Bs[kk][c4] = *(const float4*)(Bb + kk * HD + c4);
        }
        __syncthreads();

#pragma unroll
        for (int kk = 0; kk < 16; kk++) {
            float4 a03 = *(const float4*)&As[kk][row0];
            float4 a47 = *(const float4*)&As[kk][row0 + 4];
            double2 b01 = *(const double2*)&Bs[kk][col0];
            double2 b23 = *(const double2*)&Bs[kk][col0 + 4];
            unsigned long long bp[4];
            bp[0] = __double_as_longlong(b01.x);
            bp[1] = __double_as_longlong(b01.y);
            bp[2] = __double_as_longlong(b23.x);
            bp[3] = __double_as_longlong(b23.y);
            unsigned long long ap[8];
            ap[0] = bcast2(a03.x); ap[1] = bcast2(a03.y);
            ap[2] = bcast2(a03.z); ap[3] = bcast2(a03.w);
            ap[4] = bcast2(a47.x); ap[5] = bcast2(a47.y);
            ap[6] = bcast2(a47.z); ap[7] = bcast2(a47.w);
#pragma unroll
            for (int i = 0; i < 8; i++)
#pragma unroll
                for (int j = 0; j < 4; j++)
                    ffma2(acc[i][j], ap[i], bp[j]);
        }
        __syncthreads();
    }

    float bv[8];
#pragma unroll
    for (int j = 0; j < 8; j++) bv[j] = bias[col0 + j];

#pragma unroll
    for (int i = 0; i < 8; i++) {
        int g = brow + row0 + i;
        if (g < M) {
            float o[8];
#pragma unroll
            for (int j = 0; j < 4; j++) {
                float2 f = unpack2(acc[i][j]);
                o[2 * j]     = fmaxf(f.x + bv[2 * j], 0.0f);
                o[2 * j + 1] = fmaxf(f.y + bv[2 * j + 1], 0.0f);
            }
            float* op = out + (size_t)g * HD + col0;
            *(float4*)op       = make_float4(o[0], o[1], o[2], o[3]);
            *(float4*)(op + 4) = make_float4(o[4], o[5], o[6], o[7]);
        }
    }
}

// out[n] = dot(h2[n,:], Wc) + bc; one warp per node
__global__ void classify_kernel(const float* __restrict__ h, const float* __restrict__ Wc,
                                const float* __restrict__ bc, float* __restrict__ out, int M) {
    int t = blockIdx.x * blockDim.x + threadIdx.x;
    int n = t >> 5, lane = t & 31;
    if (n >= M) return;
    float4 v = *(const float4*)(h + (size_t)n * HD + lane * 4);
    float4 w = *(const float4*)(Wc + lane * 4);
    float s = v.x * w.x + v.y * w.y + v.z * w.z + v.w * w.w;
#pragma unroll
    for (int o = 16; o; o >>= 1) s += __shfl_xor_sync(0xffffffffu, s, o);
    if (lane == 0) out[n] = s + bc[0];
}

// ---------------- launch ----------------
extern "C" void kernel_launch(void* const* d_in, const int* in_sizes, int n_in,
                              void* d_out, int out_size) {
    const float* x  = (const float*)d_in[0];
    const int*   ei = (const int*)d_in[1];
    const int*   et = (const int*)d_in[2];
    const float* W1 = (const float*)d_in[3];
    const float* r1 = (const float*)d_in[4];
    const float* b1 = (const float*)d_in[5];
    const float* W2 = (const float*)d_in[6];
    const float* r2 = (const float*)d_in[7];
    const float* b2 = (const float*)d_in[8];
    const float* Wc = (const float*)d_in[9];
    const float* bc = (const float*)d_in[10];

    int M = in_sizes[0] / HD;    // 50000 nodes
    int E = in_sizes[1] / 2;     // 500000 edges
    const int* src = ei;
    const int* dst = ei + E;

    float *agg, *h1, *h2;
    int* cnt;
    cudaGetSymbolAddress((void**)&agg, g_agg);
    cudaGetSymbolAddress((void**)&cnt, g_cnt);
    cudaGetSymbolAddress((void**)&h1, g_h1);
    cudaGetSymbolAddress((void**)&h2, g_h2);

    long n4 = (long)M * RR * HD / 4;
    int mblocks = (M + 127) / 128;
    int eblocks = (E + 255) / 256;
    int sblocks = (E * 32 + 255) / 256;

    // ---- layer 1 ----
    zero_kernel<<<2048, 256>>>((float4*)agg, cnt, n4, M * RR, 1);
    count_kernel<<<eblocks, 256>>>(dst, et, cnt, E);
    scatter_kernel<<<sblocks, 256>>>(x, src, dst, et, agg, E);
    rgcn_gemm<<<mblocks, 256>>>(x, agg, cnt, r1, W1, b1, h1, M);

    // ---- layer 2 (counts unchanged; reuse) ----
    zero_kernel<<<2048, 256>>>((float4*)agg, cnt, n4, 0, 0);
    scatter_kernel<<<sblocks, 256>>>(h1, src, dst, et, agg, E);
    rgcn_gemm<<<mblocks, 256>>>(h1, agg, cnt, r2, W2, b2, h2, M);

    // ---- classifier ----
    classify_kernel<<<((M * 32) + 255) / 256, 256>>>(h2, Wc, bc, (float*)d_out, M);
}

// round 4
// speedup vs baseline: 1.0469x; 1.0469x over previous
#include <cuda_runtime.h>
#include <cuda_bf16.h>
#include <cstdint>

#define HD   128
#define RR   8
#define NMAX 50000
#define KTOT (HD + RR * HD)     // 1152
#define NCHUNK 36               // 1152 / 32
#define AST  40                 // smem row stride (bf16 elems): 32 + 8 pad

// ---------------- scratch (static device globals; no allocation) ----------------
__device__ float g_agg[(size_t)NMAX * RR * HD];     // [N, 8, 128]
__device__ int   g_cnt[NMAX * RR];
__device__ float g_h1[(size_t)NMAX * HD];
__device__ float g_h2[(size_t)NMAX * HD];
__device__ __nv_bfloat16 g_Bh1[128 * KTOT];         // B^T hi/lo: [n][k]
__device__ __nv_bfloat16 g_Bl1[128 * KTOT];
__device__ __nv_bfloat16 g_Bh2[128 * KTOT];
__device__ __nv_bfloat16 g_Bl2[128 * KTOT];

// ---------------- mma.sync / ldmatrix helpers (base PTX, sm_80+) ----------------
__device__ __forceinline__ uint32_t smem_u32(const void* p) {
    return (uint32_t)__cvta_generic_to_shared(p);
}
__device__ __forceinline__ void ldsm_x4(uint32_t* r, uint32_t addr) {
    asm volatile("ldmatrix.sync.aligned.m8n8.x4.shared.b16 {%0,%1,%2,%3}, [%4];"
                 : "=r"(r[0]), "=r"(r[1]), "=r"(r[2]), "=r"(r[3]) : "r"(addr));
}
__device__ __forceinline__ void mma16816(float* d, const uint32_t* a, const uint32_t* b) {
    asm volatile(
        "mma.sync.aligned.m16n8k16.row.col.f32.bf16.bf16.f32 "
        "{%0,%1,%2,%3}, {%4,%5,%6,%7}, {%8,%9}, {%0,%1,%2,%3};"
        : "+f"(d[0]), "+f"(d[1]), "+f"(d[2]), "+f"(d[3])
        : "r"(a[0]), "r"(a[1]), "r"(a[2]), "r"(a[3]), "r"(b[0]), "r"(b[1]));
}

// ---------------- elementwise / scatter kernels ----------------
__global__ void zero_kernel(float4* agg, int* cnt, long n4, int ncnt, int do_cnt) {
    long i = blockIdx.x * (long)blockDim.x + threadIdx.x;
    long stride = (long)gridDim.x * blockDim.x;
    float4 z = make_float4(0.f, 0.f, 0.f, 0.f);
    for (long k = i; k < n4; k += stride) agg[k] = z;
    if (do_cnt)
        for (long k = i; k < ncnt; k += stride) cnt[k] = 0;
}

__global__ void count_kernel(const int* __restrict__ dst, const int* __restrict__ et,
                             int* cnt, int E) {
    int e = blockIdx.x * blockDim.x + threadIdx.x;
    if (e < E) atomicAdd(&cnt[dst[e] * RR + et[e]], 1);
}

__global__ void scatter_kernel(const float* __restrict__ feat,
                               const int* __restrict__ src, const int* __restrict__ dst,
                               const int* __restrict__ et, float* agg, int E) {
    int t = blockIdx.x * blockDim.x + threadIdx.x;
    int e = t >> 5, lane = t & 31;
    if (e >= E) return;
    int s = src[e], d = dst[e], r = et[e];
    float4 v = *(const float4*)(feat + (size_t)s * HD + lane * 4);
    float* a = agg + (size_t)d * (RR * HD) + r * HD + lane * 4;
    asm volatile("red.global.add.v4.f32 [%0], {%1, %2, %3, %4};"
                 :: "l"(a), "f"(v.x), "f"(v.y), "f"(v.z), "f"(v.w) : "memory");
}

// weight prep: B^T[n][k] split to bf16 hi/lo.  k<128 -> root[k][n], else W[(k-128)][n]
__global__ void prep_kernel(const float* __restrict__ root, const float* __restrict__ W,
                            __nv_bfloat16* Bh, __nv_bfloat16* Bl) {
    int t = blockIdx.x * blockDim.x + threadIdx.x;
    if (t >= 128 * KTOT) return;
    int n = t / KTOT, k = t % KTOT;
    float v = (k < HD) ? root[k * HD + n] : W[(size_t)(k - HD) * HD + n];
    __nv_bfloat16 h = __float2bfloat16(v);
    float lo = v - __bfloat162float(h);
    Bh[t] = h;
    Bl[t] = __float2bfloat16(lo);
}

// ---------------- split-bf16 mma.sync GEMM ----------------
// out[128 x 128] = relu( [X | invcnt*agg] @ [root;W] + bias )
__global__ __launch_bounds__(256, 2) void rgcn_mma(
    const float* __restrict__ X, const float* __restrict__ agg,
    const int* __restrict__ cnt,
    const __nv_bfloat16* __restrict__ Bh, const __nv_bfloat16* __restrict__ Bl,
    const float* __restrict__ bias, float* __restrict__ out, int M) {

    __shared__ __nv_bfloat16 Ah_s[128][AST], Al_s[128][AST];
    __shared__ __nv_bfloat16 Bh_s[128][AST], Bl_s[128][AST];
    __shared__ float InvS[128 * RR];

    const int tid = threadIdx.x;
    const int wid = tid >> 5;
    const int lane = tid & 31;
    const int brow = blockIdx.x * 128;

    // inverse counts per (row, relation)
    for (int i = tid; i < 128 * RR; i += 256) {
        int r = i >> 3, rel = i & 7;
        int gg = brow + r;
        int c = (gg < M) ? cnt[gg * RR + rel] : 1;
        InvS[r * RR + rel] = 1.0f / (float)(c > 1 ? c : 1);
    }

    // warp tile: 4 (m) x 2 (n) warps; each warp 32 rows x 64 cols
    const int warp_m = wid & 3, warp_n = wid >> 2;
    const int mr0 = warp_m * 32, nc0 = warp_n * 64;

    // ldmatrix source addresses (k-offsets added later as bytes)
    const int alr = lane & 15, alc = (lane >> 4) << 3;
    uint32_t aA0h = smem_u32(&Ah_s[mr0 + alr][alc]);
    uint32_t aA1h = smem_u32(&Ah_s[mr0 + 16 + alr][alc]);
    uint32_t aA0l = smem_u32(&Al_s[mr0 + alr][alc]);
    uint32_t aA1l = smem_u32(&Al_s[mr0 + 16 + alr][alc]);
    // B (non-trans): lanes 0-7 -> n0-7/k0, 8-15 -> n0-7/k8, 16-23 -> n8-15/k0, 24-31 -> n8-15/k8
    const int blr = (lane & 7) + ((lane >> 4) << 3);
    const int blc = ((lane >> 3) & 1) << 3;
    uint32_t aBh[4], aBl[4];
#pragma unroll
    for (int j = 0; j < 4; j++) {
        aBh[j] = smem_u32(&Bh_s[nc0 + blr + j * 16][blc]);
        aBl[j] = smem_u32(&Bl_s[nc0 + blr + j * 16][blc]);
    }

    float acc[2][8][4];
#pragma unroll
    for (int i = 0; i < 2; i++)
#pragma unroll
        for (int j = 0; j < 8; j++)
#pragma unroll
            for (int q = 0; q < 4; q++) acc[i][j][q] = 0.f;

    const int arow = tid >> 1;            // 0..127 (also the B n-row this thread copies)
    const int aks  = (tid & 1) << 4;      // k offset 0 / 16
    const int g    = brow + arow;

    __syncthreads();

    for (int c = 0; c < NCHUNK; c++) {
        // ---- A: load fp32, scale, split hi/lo into smem ----
        const float* ap;
        float s;
        if (c < 4) { ap = X + (size_t)g * HD + c * 32 + aks; s = 1.0f; }
        else {
            ap = agg + (size_t)g * (RR * HD) + (c - 4) * 32 + aks;
            s = InvS[arow * RR + ((c - 4) >> 2)];
        }
        float4 v[4];
#pragma unroll
        for (int i = 0; i < 4; i++)
            v[i] = (g < M) ? *(const float4*)(ap + i * 4) : make_float4(0.f, 0.f, 0.f, 0.f);
        __nv_bfloat162* ah2 = (__nv_bfloat162*)&Ah_s[arow][aks];
        __nv_bfloat162* al2 = (__nv_bfloat162*)&Al_s[arow][aks];
#pragma unroll
        for (int i = 0; i < 4; i++) {
            float f0 = v[i].x * s, f1 = v[i].y * s, f2 = v[i].z * s, f3 = v[i].w * s;
            __nv_bfloat16 h0 = __float2bfloat16(f0), h1 = __float2bfloat16(f1);
            __nv_bfloat16 h2 = __float2bfloat16(f2), h3 = __float2bfloat16(f3);
            ah2[i * 2]     = __halves2bfloat162(h0, h1);
            ah2[i * 2 + 1] = __halves2bfloat162(h2, h3);
            al2[i * 2]     = __halves2bfloat162(
                __float2bfloat16(f0 - __bfloat162float(h0)),
                __float2bfloat16(f1 - __bfloat162float(h1)));
            al2[i * 2 + 1] = __halves2bfloat162(
                __float2bfloat16(f2 - __bfloat162float(h2)),
                __float2bfloat16(f3 - __bfloat162float(h3)));
        }
        // ---- B: copy pre-split bf16 chunk ----
        {
            const uint4* bh = (const uint4*)(Bh + (size_t)arow * KTOT + c * 32 + aks);
            const uint4* bl = (const uint4*)(Bl + (size_t)arow * KTOT + c * 32 + aks);
            *(uint4*)&Bh_s[arow][aks]     = bh[0];
            *(uint4*)&Bh_s[arow][aks + 8] = bh[1];
            *(uint4*)&Bl_s[arow][aks]     = bl[0];
            *(uint4*)&Bl_s[arow][aks + 8] = bl[1];
        }
        __syncthreads();

        // ---- compute: 2 k16 steps x 3 terms ----
#pragma unroll
        for (int k16 = 0; k16 < 2; k16++) {
            const int kb = k16 * 32;   // 16 elems * 2 bytes
            uint32_t Afh[2][4], Afl[2][4];
            ldsm_x4(Afh[0], aA0h + kb);
            ldsm_x4(Afh[1], aA1h + kb);
            ldsm_x4(Afl[0], aA0l + kb);
            ldsm_x4(Afl[1], aA1l + kb);
            uint32_t Bf[8][2];
#pragma unroll
            for (int j = 0; j < 4; j++) {
                uint32_t t[4];
                ldsm_x4(t, aBh[j] + kb);           // non-trans: Bs[n][k] k-contiguous
                Bf[2 * j][0] = t[0]; Bf[2 * j][1] = t[1];
                Bf[2 * j + 1][0] = t[2]; Bf[2 * j + 1][1] = t[3];
            }
#pragma unroll
            for (int mf = 0; mf < 2; mf++)
#pragma unroll
                for (int nf = 0; nf < 8; nf++) mma16816(acc[mf][nf], Afh[mf], Bf[nf]);
#pragma unroll
            for (int mf = 0; mf < 2; mf++)
#pragma unroll
                for (int nf = 0; nf < 8; nf++) mma16816(acc[mf][nf], Afl[mf], Bf[nf]);
#pragma unroll
            for (int j = 0; j < 4; j++) {
                uint32_t t[4];
                ldsm_x4(t, aBl[j] + kb);           // non-trans
                Bf[2 * j][0] = t[0]; Bf[2 * j][1] = t[1];
                Bf[2 * j + 1][0] = t[2]; Bf[2 * j + 1][1] = t[3];
            }
#pragma unroll
            for (int mf = 0; mf < 2; mf++)
#pragma unroll
                for (int nf = 0; nf < 8; nf++) mma16816(acc[mf][nf], Afh[mf], Bf[nf]);
        }
        __syncthreads();
    }

    // ---- epilogue: bias + relu + store ----
    const int er = lane >> 2, ec = (lane & 3) * 2;
    float2 bv[8];
#pragma unroll
    for (int nf = 0; nf < 8; nf++)
        bv[nf] = *(const float2*)(bias + nc0 + nf * 8 + ec);

#pragma unroll
    for (int mf = 0; mf < 2; mf++) {
#pragma unroll
        for (int half = 0; half < 2; half++) {
            int gr = brow + mr0 + mf * 16 + half * 8 + er;
            if (gr < M) {
                float* op = out + (size_t)gr * HD + nc0 + ec;
#pragma unroll
                for (int nf = 0; nf < 8; nf++) {
                    float2 o;
                    o.x = fmaxf(acc[mf][nf][half * 2]     + bv[nf].x, 0.f);
                    o.y = fmaxf(acc[mf][nf][half * 2 + 1] + bv[nf].y, 0.f);
                    *(float2*)(op + nf * 8) = o;
                }
            }
        }
    }
}

// out[n] = dot(h2[n,:], Wc) + bc; one warp per node
__global__ void classify_kernel(const float* __restrict__ h, const float* __restrict__ Wc,
                                const float* __restrict__ bc, float* __restrict__ out, int M) {
    int t = blockIdx.x * blockDim.x + threadIdx.x;
    int n = t >> 5, lane = t & 31;
    if (n >= M) return;
    float4 v = *(const float4*)(h + (size_t)n * HD + lane * 4);
    float4 w = *(const float4*)(Wc + lane * 4);
    float s = v.x * w.x + v.y * w.y + v.z * w.z + v.w * w.w;
#pragma unroll
    for (int o = 16; o; o >>= 1) s += __shfl_xor_sync(0xffffffffu, s, o);
    if (lane == 0) out[n] = s + bc[0];
}

// ---------------- launch ----------------
extern "C" void kernel_launch(void* const* d_in, const int* in_sizes, int n_in,
                              void* d_out, int out_size) {
    const float* x  = (const float*)d_in[0];
    const int*   ei = (const int*)d_in[1];
    const int*   et = (const int*)d_in[2];
    const float* W1 = (const float*)d_in[3];
    const float* r1 = (const float*)d_in[4];
    const float* b1 = (const float*)d_in[5];
    const float* W2 = (const float*)d_in[6];
    const float* r2 = (const float*)d_in[7];
    const float* b2 = (const float*)d_in[8];
    const float* Wc = (const float*)d_in[9];
    const float* bc = (const float*)d_in[10];

    int M = in_sizes[0] / HD;    // 50000
    int E = in_sizes[1] / 2;     // 500000
    const int* src = ei;
    const int* dst = ei + E;

    float *agg, *h1, *h2;
    int* cnt;
    __nv_bfloat16 *Bh1, *Bl1, *Bh2, *Bl2;
    cudaGetSymbolAddress((void**)&agg, g_agg);
    cudaGetSymbolAddress((void**)&cnt, g_cnt);
    cudaGetSymbolAddress((void**)&h1, g_h1);
    cudaGetSymbolAddress((void**)&h2, g_h2);
    cudaGetSymbolAddress((void**)&Bh1, g_Bh1);
    cudaGetSymbolAddress((void**)&Bl1, g_Bl1);
    cudaGetSymbolAddress((void**)&Bh2, g_Bh2);
    cudaGetSymbolAddress((void**)&Bl2, g_Bl2);

    long n4 = (long)M * RR * HD / 4;
    int mblocks = (M + 127) / 128;                 // 391
    int eblocks = (E + 255) / 256;
    int sblocks = (E * 32 + 255) / 256;
    int pblocks = (128 * KTOT + 255) / 256;

    // weight prep (static per call)
    prep_kernel<<<pblocks, 256>>>(r1, W1, Bh1, Bl1);
    prep_kernel<<<pblocks, 256>>>(r2, W2, Bh2, Bl2);

    // ---- layer 1 ----
    zero_kernel<<<2048, 256>>>((float4*)agg, cnt, n4, M * RR, 1);
    count_kernel<<<eblocks, 256>>>(dst, et, cnt, E);
    scatter_kernel<<<sblocks, 256>>>(x, src, dst, et, agg, E);
    rgcn_mma<<<mblocks, 256>>>(x, agg, cnt, Bh1, Bl1, b1, h1, M);

    // ---- layer 2 (counts unchanged) ----
    zero_kernel<<<2048, 256>>>((float4*)agg, cnt, n4, 0, 0);
    scatter_kernel<<<sblocks, 256>>>(h1, src, dst, et, agg, E);
    rgcn_mma<<<mblocks, 256>>>(h1, agg, cnt, Bh2, Bl2, b2, h2, M);

    // ---- classifier ----
    classify_kernel<<<((M * 32) + 255) / 256, 256>>>(h2, Wc, bc, (float*)d_out, M);
}

// round 5
// speedup vs baseline: 1.8923x; 1.8076x over previous
#include <cuda_runtime.h>
#include <cuda_bf16.h>
#include <cstdint>

#define HD   128
#define RR   8
#define NMAX 50000
#define KTOT (HD + RR * HD)     // 1152
#define NCHUNK 36               // 1152 / 32
#define AST  40                 // smem row stride (bf16 elems): 32 + 8 pad

// ---------------- scratch (static device globals; no allocation) ----------------
__device__ float g_agg[(size_t)NMAX * RR * HD];     // [N, 8, 128]
__device__ int   g_cnt[NMAX * RR];
__device__ float g_h1[(size_t)NMAX * HD];
__device__ float g_h2[(size_t)NMAX * HD];
__device__ __nv_bfloat16 g_Bh1[128 * KTOT];         // B^T hi/lo: [n][k]
__device__ __nv_bfloat16 g_Bl1[128 * KTOT];
__device__ __nv_bfloat16 g_Bh2[128 * KTOT];
__device__ __nv_bfloat16 g_Bl2[128 * KTOT];

// ---------------- mma.sync / ldmatrix / cp.async helpers (base PTX, sm_80+) -----
__device__ __forceinline__ uint32_t smem_u32(const void* p) {
    return (uint32_t)__cvta_generic_to_shared(p);
}
__device__ __forceinline__ void ldsm_x4(uint32_t* r, uint32_t addr) {
    asm volatile("ldmatrix.sync.aligned.m8n8.x4.shared.b16 {%0,%1,%2,%3}, [%4];"
                 : "=r"(r[0]), "=r"(r[1]), "=r"(r[2]), "=r"(r[3]) : "r"(addr));
}
__device__ __forceinline__ void mma16816(float* d, const uint32_t* a, const uint32_t* b) {
    asm volatile(
        "mma.sync.aligned.m16n8k16.row.col.f32.bf16.bf16.f32 "
        "{%0,%1,%2,%3}, {%4,%5,%6,%7}, {%8,%9}, {%0,%1,%2,%3};"
        : "+f"(d[0]), "+f"(d[1]), "+f"(d[2]), "+f"(d[3])
        : "r"(a[0]), "r"(a[1]), "r"(a[2]), "r"(a[3]), "r"(b[0]), "r"(b[1]));
}
__device__ __forceinline__ void cp_async16(uint32_t smem_dst, const void* gptr) {
    asm volatile("cp.async.cg.shared.global [%0], [%1], 16;"
                 :: "r"(smem_dst), "l"(gptr));
}
__device__ __forceinline__ void cp_commit() {
    asm volatile("cp.async.commit_group;");
}
__device__ __forceinline__ void cp_wait0() {
    asm volatile("cp.async.wait_group 0;");
}

// ---------------- elementwise / scatter kernels ----------------
__global__ void zero_kernel(float4* agg, int* cnt, long n4, int ncnt, int do_cnt) {
    long i = blockIdx.x * (long)blockDim.x + threadIdx.x;
    long stride = (long)gridDim.x * blockDim.x;
    float4 z = make_float4(0.f, 0.f, 0.f, 0.f);
    for (long k = i; k < n4; k += stride) agg[k] = z;
    if (do_cnt)
        for (long k = i; k < ncnt; k += stride) cnt[k] = 0;
}

__global__ void count_kernel(const int* __restrict__ dst, const int* __restrict__ et,
                             int* cnt, int E) {
    int e = blockIdx.x * blockDim.x + threadIdx.x;
    if (e < E) atomicAdd(&cnt[dst[e] * RR + et[e]], 1);
}

__global__ void scatter_kernel(const float* __restrict__ feat,
                               const int* __restrict__ src, const int* __restrict__ dst,
                               const int* __restrict__ et, float* agg, int E) {
    int t = blockIdx.x * blockDim.x + threadIdx.x;
    int e = t >> 5, lane = t & 31;
    if (e >= E) return;
    int s = src[e], d = dst[e], r = et[e];
    float4 v = *(const float4*)(feat + (size_t)s * HD + lane * 4);
    float* a = agg + (size_t)d * (RR * HD) + r * HD + lane * 4;
    asm volatile("red.global.add.v4.f32 [%0], {%1, %2, %3, %4};"
                 :: "l"(a), "f"(v.x), "f"(v.y), "f"(v.z), "f"(v.w) : "memory");
}

// weight prep: B^T[n][k] split to bf16 hi/lo.  k<128 -> root[k][n], else W[(k-128)][n]
__global__ void prep_kernel(const float* __restrict__ root, const float* __restrict__ W,
                            __nv_bfloat16* Bh, __nv_bfloat16* Bl) {
    int t = blockIdx.x * blockDim.x + threadIdx.x;
    if (t >= 128 * KTOT) return;
    int n = t / KTOT, k = t % KTOT;
    float v = (k < HD) ? root[k * HD + n] : W[(size_t)(k - HD) * HD + n];
    __nv_bfloat16 h = __float2bfloat16(v);
    float lo = v - __bfloat162float(h);
    Bh[t] = h;
    Bl[t] = __float2bfloat16(lo);
}

// ---------------- split-bf16 mma.sync GEMM, double-buffered pipeline ----------------
// out[128 x 128] = relu( [X | invcnt*agg] @ [root;W] + bias )
__global__ __launch_bounds__(256, 2) void rgcn_mma(
    const float* __restrict__ X, const float* __restrict__ agg,
    const int* __restrict__ cnt,
    const __nv_bfloat16* __restrict__ Bh, const __nv_bfloat16* __restrict__ Bl,
    const float* __restrict__ bias, float* __restrict__ out, int M) {

    __shared__ __nv_bfloat16 Ah_s[2][128][AST], Al_s[2][128][AST];
    __shared__ __nv_bfloat16 Bh_s[2][128][AST], Bl_s[2][128][AST];
    __shared__ float InvS[128 * RR];

    const int tid = threadIdx.x;
    const int wid = tid >> 5;
    const int lane = tid & 31;
    const int brow = blockIdx.x * 128;

    for (int i = tid; i < 128 * RR; i += 256) {
        int r = i >> 3, rel = i & 7;
        int gg = brow + r;
        int c = (gg < M) ? cnt[gg * RR + rel] : 1;
        InvS[r * RR + rel] = 1.0f / (float)(c > 1 ? c : 1);
    }

    const int warp_m = wid & 3, warp_n = wid >> 2;
    const int mr0 = warp_m * 32, nc0 = warp_n * 64;

    // ldmatrix lane addressing (per-buffer base computed in loop via buf offset)
    const int alr = lane & 15, alc = (lane >> 4) << 3;
    const uint32_t aA0h = smem_u32(&Ah_s[0][mr0 + alr][alc]);
    const uint32_t aA1h = smem_u32(&Ah_s[0][mr0 + 16 + alr][alc]);
    const uint32_t aA0l = smem_u32(&Al_s[0][mr0 + alr][alc]);
    const uint32_t aA1l = smem_u32(&Al_s[0][mr0 + 16 + alr][alc]);
    const int blr = (lane & 7) + ((lane >> 4) << 3);
    const int blc = ((lane >> 3) & 1) << 3;
    uint32_t aBhx[4], aBlx[4];
#pragma unroll
    for (int j = 0; j < 4; j++) {
        aBhx[j] = smem_u32(&Bh_s[0][nc0 + blr + j * 16][blc]);
        aBlx[j] = smem_u32(&Bl_s[0][nc0 + blr + j * 16][blc]);
    }
    const uint32_t BUFO = 128 * AST * 2;    // bytes per buffer stage

    float acc[2][8][4];
#pragma unroll
    for (int i = 0; i < 2; i++)
#pragma unroll
        for (int j = 0; j < 8; j++)
#pragma unroll
            for (int q = 0; q < 4; q++) acc[i][j][q] = 0.f;

    const int arow = tid >> 1;            // 0..127
    const int aks  = (tid & 1) << 4;      // k offset 0 / 16
    const int g    = brow + arow;

    // ---- pipeline helpers (lambdas) ----
    auto loadA = [&](int c, float4* v, float& s) {
        const float* ap;
        if (c < 4) { ap = X + (size_t)g * HD + c * 32 + aks; s = 1.0f; }
        else {
            ap = agg + (size_t)g * (RR * HD) + (c - 4) * 32 + aks;
            s = InvS[arow * RR + ((c - 4) >> 2)];
        }
#pragma unroll
        for (int i = 0; i < 4; i++)
            v[i] = (g < M) ? *(const float4*)(ap + i * 4) : make_float4(0.f, 0.f, 0.f, 0.f);
    };
    auto cpB = [&](int c, int buf) {
        const char* bh = (const char*)(Bh + (size_t)arow * KTOT + c * 32 + aks);
        const char* bl = (const char*)(Bl + (size_t)arow * KTOT + c * 32 + aks);
        uint32_t dh = smem_u32(&Bh_s[buf][arow][aks]);
        uint32_t dl = smem_u32(&Bl_s[buf][arow][aks]);
        cp_async16(dh, bh);
        cp_async16(dh + 16, bh + 16);
        cp_async16(dl, bl);
        cp_async16(dl + 16, bl + 16);
    };
    auto storeA = [&](const float4* v, float s, int buf) {
        __nv_bfloat162* ah2 = (__nv_bfloat162*)&Ah_s[buf][arow][aks];
        __nv_bfloat162* al2 = (__nv_bfloat162*)&Al_s[buf][arow][aks];
#pragma unroll
        for (int i = 0; i < 4; i++) {
            float f0 = v[i].x * s, f1 = v[i].y * s, f2 = v[i].z * s, f3 = v[i].w * s;
            __nv_bfloat16 h0 = __float2bfloat16(f0), h1 = __float2bfloat16(f1);
            __nv_bfloat16 h2 = __float2bfloat16(f2), h3 = __float2bfloat16(f3);
            ah2[i * 2]     = __halves2bfloat162(h0, h1);
            ah2[i * 2 + 1] = __halves2bfloat162(h2, h3);
            al2[i * 2]     = __halves2bfloat162(
                __float2bfloat16(f0 - __bfloat162float(h0)),
                __float2bfloat16(f1 - __bfloat162float(h1)));
            al2[i * 2 + 1] = __halves2bfloat162(
                __float2bfloat16(f2 - __bfloat162float(h2)),
                __float2bfloat16(f3 - __bfloat162float(h3)));
        }
    };

    // ---- prologue: fill buffer 0 with chunk 0 ----
    {
        float4 pv[4]; float ps;
        loadA(0, pv, ps);
        cpB(0, 0);
        cp_commit();
        storeA(pv, ps, 0);
        cp_wait0();
    }
    __syncthreads();

    // ---- mainloop ----
    for (int c = 0; c < NCHUNK; c++) {
        const int buf = c & 1;
        const uint32_t bo = buf ? BUFO : 0;

        float4 pv[4]; float ps;
        if (c + 1 < NCHUNK) {
            loadA(c + 1, pv, ps);               // global->regs (latency hidden by MMAs)
            cpB(c + 1, buf ^ 1);                // global->smem async
            cp_commit();
        }

        // ---- compute: 2 k16 steps x 3 terms on buffer `buf` ----
#pragma unroll
        for (int k16 = 0; k16 < 2; k16++) {
            const uint32_t kb = bo + k16 * 32;
            uint32_t Afh[2][4], Afl[2][4];
            ldsm_x4(Afh[0], aA0h + kb);
            ldsm_x4(Afh[1], aA1h + kb);
            ldsm_x4(Afl[0], aA0l + kb);
            ldsm_x4(Afl[1], aA1l + kb);
            uint32_t Bf[8][2];
#pragma unroll
            for (int j = 0; j < 4; j++) {
                uint32_t t[4];
                ldsm_x4(t, aBhx[j] + kb);
                Bf[2 * j][0] = t[0]; Bf[2 * j][1] = t[1];
                Bf[2 * j + 1][0] = t[2]; Bf[2 * j + 1][1] = t[3];
            }
#pragma unroll
            for (int mf = 0; mf < 2; mf++)
#pragma unroll
                for (int nf = 0; nf < 8; nf++) mma16816(acc[mf][nf], Afh[mf], Bf[nf]);
#pragma unroll
            for (int mf = 0; mf < 2; mf++)
#pragma unroll
                for (int nf = 0; nf < 8; nf++) mma16816(acc[mf][nf], Afl[mf], Bf[nf]);
#pragma unroll
            for (int j = 0; j < 4; j++) {
                uint32_t t[4];
                ldsm_x4(t, aBlx[j] + kb);
                Bf[2 * j][0] = t[0]; Bf[2 * j][1] = t[1];
                Bf[2 * j + 1][0] = t[2]; Bf[2 * j + 1][1] = t[3];
            }
#pragma unroll
            for (int mf = 0; mf < 2; mf++)
#pragma unroll
                for (int nf = 0; nf < 8; nf++) mma16816(acc[mf][nf], Afh[mf], Bf[nf]);
        }

        if (c + 1 < NCHUNK) {
            storeA(pv, ps, buf ^ 1);            // regs->smem (other buffer)
            cp_wait0();
        }
        __syncthreads();
    }

    // ---- epilogue: bias + relu + store ----
    const int er = lane >> 2, ec = (lane & 3) * 2;
    float2 bv[8];
#pragma unroll
    for (int nf = 0; nf < 8; nf++)
        bv[nf] = *(const float2*)(bias + nc0 + nf * 8 + ec);

#pragma unroll
    for (int mf = 0; mf < 2; mf++) {
#pragma unroll
        for (int half = 0; half < 2; half++) {
            int gr = brow + mr0 + mf * 16 + half * 8 + er;
            if (gr < M) {
                float* op = out + (size_t)gr * HD + nc0 + ec;
#pragma unroll
                for (int nf = 0; nf < 8; nf++) {
                    float2 o;
                    o.x = fmaxf(acc[mf][nf][half * 2]     + bv[nf].x, 0.f);
                    o.y = fmaxf(acc[mf][nf][half * 2 + 1] + bv[nf].y, 0.f);
                    *(float2*)(op + nf * 8) = o;
                }
            }
        }
    }
}

// out[n] = dot(h2[n,:], Wc) + bc; one warp per node
__global__ void classify_kernel(const float* __restrict__ h, const float* __restrict__ Wc,
                                const float* __restrict__ bc, float* __restrict__ out, int M) {
    int t = blockIdx.x * blockDim.x + threadIdx.x;
    int n = t >> 5, lane = t & 31;
    if (n >= M) return;
    float4 v = *(const float4*)(h + (size_t)n * HD + lane * 4);
    float4 w = *(const float4*)(Wc + lane * 4);
    float s = v.x * w.x + v.y * w.y + v.z * w.z + v.w * w.w;
#pragma unroll
    for (int o = 16; o; o >>= 1) s += __shfl_xor_sync(0xffffffffu, s, o);
    if (lane == 0) out[n] = s + bc[0];
}

// ---------------- launch ----------------
extern "C" void kernel_launch(void* const* d_in, const int* in_sizes, int n_in,
                              void* d_out, int out_size) {
    const float* x  = (const float*)d_in[0];
    const int*   ei = (const int*)d_in[1];
    const int*   et = (const int*)d_in[2];
    const float* W1 = (const float*)d_in[3];
    const float* r1 = (const float*)d_in[4];
    const float* b1 = (const float*)d_in[5];
    const float* W2 = (const float*)d_in[6];
    const float* r2 = (const float*)d_in[7];
    const float* b2 = (const float*)d_in[8];
    const float* Wc = (const float*)d_in[9];
    const float* bc = (const float*)d_in[10];

    int M = in_sizes[0] / HD;    // 50000
    int E = in_sizes[1] / 2;     // 500000
    const int* src = ei;
    const int* dst = ei + E;

    float *agg, *h1, *h2;
    int* cnt;
    __nv_bfloat16 *Bh1, *Bl1, *Bh2, *Bl2;
    cudaGetSymbolAddress((void**)&agg, g_agg);
    cudaGetSymbolAddress((void**)&cnt, g_cnt);
    cudaGetSymbolAddress((void**)&h1, g_h1);
    cudaGetSymbolAddress((void**)&h2, g_h2);
    cudaGetSymbolAddress((void**)&Bh1, g_Bh1);
    cudaGetSymbolAddress((void**)&Bl1, g_Bl1);
    cudaGetSymbolAddress((void**)&Bh2, g_Bh2);
    cudaGetSymbolAddress((void**)&Bl2, g_Bl2);

    long n4 = (long)M * RR * HD / 4;
    int mblocks = (M + 127) / 128;                 // 391
    int eblocks = (E + 255) / 256;
    int sblocks = (E * 32 + 255) / 256;
    int pblocks = (128 * KTOT + 255) / 256;

    // weight prep (static per call)
    prep_kernel<<<pblocks, 256>>>(r1, W1, Bh1, Bl1);
    prep_kernel<<<pblocks, 256>>>(r2, W2, Bh2, Bl2);

    // ---- layer 1 ----
    zero_kernel<<<2048, 256>>>((float4*)agg, cnt, n4, M * RR, 1);
    count_kernel<<<eblocks, 256>>>(dst, et, cnt, E);
    scatter_kernel<<<sblocks, 256>>>(x, src, dst, et, agg, E);
    rgcn_mma<<<mblocks, 256>>>(x, agg, cnt, Bh1, Bl1, b1, h1, M);

    // ---- layer 2 (counts unchanged) ----
    zero_kernel<<<2048, 256>>>((float4*)agg, cnt, n4, 0, 0);
    scatter_kernel<<<sblocks, 256>>>(h1, src, dst, et, agg, E);
    rgcn_mma<<<mblocks, 256>>>(h1, agg, cnt, Bh2, Bl2, b2, h2, M);

    // ---- classifier ----
    classify_kernel<<<((M * 32) + 255) / 256, 256>>>(h2, Wc, bc, (float*)d_out, M);
}

// round 6
// speedup vs baseline: 2.3801x; 1.2578x over previous
#include <cuda_runtime.h>
#include <cuda_bf16.h>
#include <cstdint>

#define HD   128
#define RR   8
#define NMAX 50000
#define EMAX 500000
#define NK   (NMAX * RR)        // 400000 bins
#define KTOT (HD + RR * HD)     // 1152
#define NCHUNK 36               // 1152 / 32
#define AST  40                 // smem row stride (bf16 elems): 32 + 8 pad

// ---------------- scratch (static device globals; no allocation) ----------------
__device__ float g_agg[(size_t)NMAX * RR * HD];     // [N, 8, 128]
__device__ int   g_cnt[NK];
__device__ int   g_off[NK];
__device__ int   g_cur[NK];
__device__ int   g_bsum[512];
__device__ int   g_esrc[EMAX];
__device__ float g_h1[(size_t)NMAX * HD];
__device__ float g_h2[(size_t)NMAX * HD];
__device__ __nv_bfloat16 g_Bh1[128 * KTOT];         // B^T hi/lo: [n][k]
__device__ __nv_bfloat16 g_Bl1[128 * KTOT];
__device__ __nv_bfloat16 g_Bh2[128 * KTOT];
__device__ __nv_bfloat16 g_Bl2[128 * KTOT];

// ---------------- mma.sync / ldmatrix / cp.async helpers (base PTX, sm_80+) -----
__device__ __forceinline__ uint32_t smem_u32(const void* p) {
    return (uint32_t)__cvta_generic_to_shared(p);
}
__device__ __forceinline__ void ldsm_x4(uint32_t* r, uint32_t addr) {
    asm volatile("ldmatrix.sync.aligned.m8n8.x4.shared.b16 {%0,%1,%2,%3}, [%4];"
                 : "=r"(r[0]), "=r"(r[1]), "=r"(r[2]), "=r"(r[3]) : "r"(addr));
}
__device__ __forceinline__ void mma16816(float* d, const uint32_t* a, const uint32_t* b) {
    asm volatile(
        "mma.sync.aligned.m16n8k16.row.col.f32.bf16.bf16.f32 "
        "{%0,%1,%2,%3}, {%4,%5,%6,%7}, {%8,%9}, {%0,%1,%2,%3};"
        : "+f"(d[0]), "+f"(d[1]), "+f"(d[2]), "+f"(d[3])
        : "r"(a[0]), "r"(a[1]), "r"(a[2]), "r"(a[3]), "r"(b[0]), "r"(b[1]));
}
__device__ __forceinline__ void cp_async16(uint32_t smem_dst, const void* gptr) {
    asm volatile("cp.async.cg.shared.global [%0], [%1], 16;"
                 :: "r"(smem_dst), "l"(gptr));
}
__device__ __forceinline__ void cp_commit() {
    asm volatile("cp.async.commit_group;");
}
__device__ __forceinline__ void cp_wait0() {
    asm volatile("cp.async.wait_group 0;");
}

// ---------------- CSR build: count -> scan -> place ----------------
__global__ void count_kernel(const int* __restrict__ dst, const int* __restrict__ et,
                             int* cnt, int E) {
    int e = blockIdx.x * blockDim.x + threadIdx.x;
    if (e < E) atomicAdd(&cnt[dst[e] * RR + et[e]], 1);
}

__global__ void scan1_kernel(const int* __restrict__ cnt, int* bsum, int nk) {
    __shared__ int sh[256];
    int b = blockIdx.x, t = threadIdx.x;
    int base = b * 1024 + t * 4;
    int s = 0;
    if (base + 3 < nk) {
        int4 v = *(const int4*)(cnt + base);
        s = v.x + v.y + v.z + v.w;
    } else {
        for (int j = 0; j < 4; j++) if (base + j < nk) s += cnt[base + j];
    }
    sh[t] = s; __syncthreads();
    for (int o = 128; o; o >>= 1) { if (t < o) sh[t] += sh[t + o]; __syncthreads(); }
    if (t == 0) bsum[b] = sh[0];
}

__global__ void scan2_kernel(int* bsum, int nb) {
    __shared__ int sh[512];
    int t = threadIdx.x;
    int v = (t < nb) ? bsum[t] : 0;
    sh[t] = v; __syncthreads();
    for (int o = 1; o < 512; o <<= 1) {
        int add = (t >= o) ? sh[t - o] : 0;
        __syncthreads();
        sh[t] += add;
        __syncthreads();
    }
    if (t < nb) bsum[t] = sh[t] - v;   // exclusive
}

__global__ void scan3_kernel(const int* __restrict__ cnt, const int* __restrict__ bsum,
                             int* off, int* cur, int nk) {
    __shared__ int sh[256];
    int b = blockIdx.x, t = threadIdx.x;
    int base = b * 1024 + t * 4;
    int v[4] = {0, 0, 0, 0};
    if (base + 3 < nk) {
        int4 q = *(const int4*)(cnt + base);
        v[0] = q.x; v[1] = q.y; v[2] = q.z; v[3] = q.w;
    } else {
        for (int j = 0; j < 4; j++) if (base + j < nk) v[j] = cnt[base + j];
    }
    int ts = v[0] + v[1] + v[2] + v[3];
    sh[t] = ts; __syncthreads();
    for (int o = 1; o < 256; o <<= 1) {
        int add = (t >= o) ? sh[t - o] : 0;
        __syncthreads();
        sh[t] += add;
        __syncthreads();
    }
    int excl = sh[t] - ts + bsum[b];
    int o0 = excl, o1 = o0 + v[0], o2 = o1 + v[1], o3 = o2 + v[2];
    if (base + 3 < nk) {
        *(int4*)(off + base) = make_int4(o0, o1, o2, o3);
        *(int4*)(cur + base) = make_int4(o0, o1, o2, o3);
    } else {
        int oo[4] = {o0, o1, o2, o3};
        for (int j = 0; j < 4; j++)
            if (base + j < nk) { off[base + j] = oo[j]; cur[base + j] = oo[j]; }
    }
}

__global__ void place_kernel(const int* __restrict__ src, const int* __restrict__ dst,
                             const int* __restrict__ et, int* cur, int* esrc, int E) {
    int e = blockIdx.x * blockDim.x + threadIdx.x;
    if (e >= E) return;
    int key = dst[e] * RR + et[e];
    int pos = atomicAdd(&cur[key], 1);
    esrc[pos] = src[e];
}

// ---------------- atomic-free aggregation: warp per dst node ----------------
// After place, cur[key] == segment end. Writes only nonempty (dst,rel) slots.
__global__ void agg_kernel(const float* __restrict__ feat, const int* __restrict__ esrc,
                           const int* __restrict__ off, const int* __restrict__ cur,
                           float* __restrict__ agg, int M) {
    int w = (blockIdx.x * blockDim.x + threadIdx.x) >> 5;
    int lane = threadIdx.x & 31;
    if (w >= M) return;
#pragma unroll
    for (int rel = 0; rel < RR; rel++) {
        int key = w * RR + rel;
        int s0 = off[key], s1 = cur[key];
        if (s0 >= s1) continue;
        float4 acc = make_float4(0.f, 0.f, 0.f, 0.f);
        int snext = esrc[s0];
        for (int e = s0; e < s1; e++) {
            int sc = snext;
            if (e + 1 < s1) snext = esrc[e + 1];
            float4 v = *(const float4*)(feat + (size_t)sc * HD + lane * 4);
            acc.x += v.x; acc.y += v.y; acc.z += v.z; acc.w += v.w;
        }
        *(float4*)(agg + (size_t)w * (RR * HD) + rel * HD + lane * 4) = acc;
    }
}

// weight prep: B^T[n][k] split to bf16 hi/lo.  k<128 -> root[k][n], else W[(k-128)][n]
__global__ void prep_kernel(const float* __restrict__ root, const float* __restrict__ W,
                            __nv_bfloat16* Bh, __nv_bfloat16* Bl) {
    int t = blockIdx.x * blockDim.x + threadIdx.x;
    if (t >= 128 * KTOT) return;
    int n = t / KTOT, k = t % KTOT;
    float v = (k < HD) ? root[k * HD + n] : W[(size_t)(k - HD) * HD + n];
    __nv_bfloat16 h = __float2bfloat16(v);
    float lo = v - __bfloat162float(h);
    Bh[t] = h;
    Bl[t] = __float2bfloat16(lo);
}

// ---------------- split-bf16 mma.sync GEMM, double-buffered pipeline ----------------
// out[128 x 128] = relu( [X | invcnt*agg] @ [root;W] + bias )
// InvS==0 masks empty (row,rel) slots -> stale agg contents are neutralized.
__global__ __launch_bounds__(256, 2) void rgcn_mma(
    const float* __restrict__ X, const float* __restrict__ agg,
    const int* __restrict__ cnt,
    const __nv_bfloat16* __restrict__ Bh, const __nv_bfloat16* __restrict__ Bl,
    const float* __restrict__ bias, float* __restrict__ out, int M) {

    __shared__ __nv_bfloat16 Ah_s[2][128][AST], Al_s[2][128][AST];
    __shared__ __nv_bfloat16 Bh_s[2][128][AST], Bl_s[2][128][AST];
    __shared__ float InvS[128 * RR];

    const int tid = threadIdx.x;
    const int wid = tid >> 5;
    const int lane = tid & 31;
    const int brow = blockIdx.x * 128;

    for (int i = tid; i < 128 * RR; i += 256) {
        int r = i >> 3, rel = i & 7;
        int gg = brow + r;
        int c = (gg < M) ? cnt[gg * RR + rel] : 0;
        InvS[r * RR + rel] = (c > 0) ? 1.0f / (float)c : 0.0f;
    }

    const int warp_m = wid & 3, warp_n = wid >> 2;
    const int mr0 = warp_m * 32, nc0 = warp_n * 64;

    const int alr = lane & 15, alc = (lane >> 4) << 3;
    const uint32_t aA0h = smem_u32(&Ah_s[0][mr0 + alr][alc]);
    const uint32_t aA1h = smem_u32(&Ah_s[0][mr0 + 16 + alr][alc]);
    const uint32_t aA0l = smem_u32(&Al_s[0][mr0 + alr][alc]);
    const uint32_t aA1l = smem_u32(&Al_s[0][mr0 + 16 + alr][alc]);
    const int blr = (lane & 7) + ((lane >> 4) << 3);
    const int blc = ((lane >> 3) & 1) << 3;
    uint32_t aBhx[4], aBlx[4];
#pragma unroll
    for (int j = 0; j < 4; j++) {
        aBhx[j] = smem_u32(&Bh_s[0][nc0 + blr + j * 16][blc]);
        aBlx[j] = smem_u32(&Bl_s[0][nc0 + blr + j * 16][blc]);
    }
    const uint32_t BUFO = 128 * AST * 2;    // bytes per buffer stage

    float acc[2][8][4];
#pragma unroll
    for (int i = 0; i < 2; i++)
#pragma unroll
        for (int j = 0; j < 8; j++)
#pragma unroll
            for (int q = 0; q < 4; q++) acc[i][j][q] = 0.f;

    const int arow = tid >> 1;            // 0..127
    const int aks  = (tid & 1) << 4;      // k offset 0 / 16
    const int g    = brow + arow;

    auto loadA = [&](int c, float4* v, float& s) {
        const float* ap;
        if (c < 4) { ap = X + (size_t)g * HD + c * 32 + aks; s = 1.0f; }
        else {
            ap = agg + (size_t)g * (RR * HD) + (c - 4) * 32 + aks;
            s = InvS[arow * RR + ((c - 4) >> 2)];
        }
#pragma unroll
        for (int i = 0; i < 4; i++)
            v[i] = (g < M) ? *(const float4*)(ap + i * 4) : make_float4(0.f, 0.f, 0.f, 0.f);
    };
    auto cpB = [&](int c, int buf) {
        const char* bh = (const char*)(Bh + (size_t)arow * KTOT + c * 32 + aks);
        const char* bl = (const char*)(Bl + (size_t)arow * KTOT + c * 32 + aks);
        uint32_t dh = smem_u32(&Bh_s[buf][arow][aks]);
        uint32_t dl = smem_u32(&Bl_s[buf][arow][aks]);
        cp_async16(dh, bh);
        cp_async16(dh + 16, bh + 16);
        cp_async16(dl, bl);
        cp_async16(dl + 16, bl + 16);
    };
    auto storeA = [&](const float4* v, float s, int buf) {
        __nv_bfloat162* ah2 = (__nv_bfloat162*)&Ah_s[buf][arow][aks];
        __nv_bfloat162* al2 = (__nv_bfloat162*)&Al_s[buf][arow][aks];
#pragma unroll
        for (int i = 0; i < 4; i++) {
            float f0 = v[i].x * s, f1 = v[i].y * s, f2 = v[i].z * s, f3 = v[i].w * s;
            __nv_bfloat16 h0 = __float2bfloat16(f0), h1 = __float2bfloat16(f1);
            __nv_bfloat16 h2 = __float2bfloat16(f2), h3 = __float2bfloat16(f3);
            ah2[i * 2]     = __halves2bfloat162(h0, h1);
            ah2[i * 2 + 1] = __halves2bfloat162(h2, h3);
            al2[i * 2]     = __halves2bfloat162(
                __float2bfloat16(f0 - __bfloat162float(h0)),
                __float2bfloat16(f1 - __bfloat162float(h1)));
            al2[i * 2 + 1] = __halves2bfloat162(
                __float2bfloat16(f2 - __bfloat162float(h2)),
                __float2bfloat16(f3 - __bfloat162float(h3)));
        }
    };

    // ---- prologue: fill buffer 0 with chunk 0 ----
    {
        float4 pv[4]; float ps;
        loadA(0, pv, ps);
        cpB(0, 0);
        cp_commit();
        storeA(pv, ps, 0);
        cp_wait0();
    }
    __syncthreads();

    // ---- mainloop ----
    for (int c = 0; c < NCHUNK; c++) {
        const int buf = c & 1;
        const uint32_t bo = buf ? BUFO : 0;

        float4 pv[4]; float ps;
        if (c + 1 < NCHUNK) {
            loadA(c + 1, pv, ps);
            cpB(c + 1, buf ^ 1);
            cp_commit();
        }

#pragma unroll
        for (int k16 = 0; k16 < 2; k16++) {
            const uint32_t kb = bo + k16 * 32;
            uint32_t Afh[2][4], Afl[2][4];
            ldsm_x4(Afh[0], aA0h + kb);
            ldsm_x4(Afh[1], aA1h + kb);
            ldsm_x4(Afl[0], aA0l + kb);
            ldsm_x4(Afl[1], aA1l + kb);
            uint32_t Bf[8][2];
#pragma unroll
            for (int j = 0; j < 4; j++) {
                uint32_t t[4];
                ldsm_x4(t, aBhx[j] + kb);
                Bf[2 * j][0] = t[0]; Bf[2 * j][1] = t[1];
                Bf[2 * j + 1][0] = t[2]; Bf[2 * j + 1][1] = t[3];
            }
#pragma unroll
            for (int mf = 0; mf < 2; mf++)
#pragma unroll
                for (int nf = 0; nf < 8; nf++) mma16816(acc[mf][nf], Afh[mf], Bf[nf]);
#pragma unroll
            for (int mf = 0; mf < 2; mf++)
#pragma unroll
                for (int nf = 0; nf < 8; nf++) mma16816(acc[mf][nf], Afl[mf], Bf[nf]);
#pragma unroll
            for (int j = 0; j < 4; j++) {
                uint32_t t[4];
                ldsm_x4(t, aBlx[j] + kb);
                Bf[2 * j][0] = t[0]; Bf[2 * j][1] = t[1];
                Bf[2 * j + 1][0] = t[2]; Bf[2 * j + 1][1] = t[3];
            }
#pragma unroll
            for (int mf = 0; mf < 2; mf++)
#pragma unroll
                for (int nf = 0; nf < 8; nf++) mma16816(acc[mf][nf], Afh[mf], Bf[nf]);
        }

        if (c + 1 < NCHUNK) {
            storeA(pv, ps, buf ^ 1);
            cp_wait0();
        }
        __syncthreads();
    }

    // ---- epilogue: bias + relu + store ----
    const int er = lane >> 2, ec = (lane & 3) * 2;
    float2 bv[8];
#pragma unroll
    for (int nf = 0; nf < 8; nf++)
        bv[nf] = *(const float2*)(bias + nc0 + nf * 8 + ec);

#pragma unroll
    for (int mf = 0; mf < 2; mf++) {
#pragma unroll
        for (int half = 0; half < 2; half++) {
            int gr = brow + mr0 + mf * 16 + half * 8 + er;
            if (gr < M) {
                float* op = out + (size_t)gr * HD + nc0 + ec;
#pragma unroll
                for (int nf = 0; nf < 8; nf++) {
                    float2 o;
                    o.x = fmaxf(acc[mf][nf][half * 2]     + bv[nf].x, 0.f);
                    o.y = fmaxf(acc[mf][nf][half * 2 + 1] + bv[nf].y, 0.f);
                    *(float2*)(op + nf * 8) = o;
                }
            }
        }
    }
}

// out[n] = dot(h2[n,:], Wc) + bc; one warp per node
__global__ void classify_kernel(const float* __restrict__ h, const float* __restrict__ Wc,
                                const float* __restrict__ bc, float* __restrict__ out, int M) {
    int t = blockIdx.x * blockDim.x + threadIdx.x;
    int n = t >> 5, lane = t & 31;
    if (n >= M) return;
    float4 v = *(const float4*)(h + (size_t)n * HD + lane * 4);
    float4 w = *(const float4*)(Wc + lane * 4);
    float s = v.x * w.x + v.y * w.y + v.z * w.z + v.w * w.w;
#pragma unroll
    for (int o = 16; o; o >>= 1) s += __shfl_xor_sync(0xffffffffu, s, o);
    if (lane == 0) out[n] = s + bc[0];
}

// ---------------- launch ----------------
extern "C" void kernel_launch(void* const* d_in, const int* in_sizes, int n_in,
                              void* d_out, int out_size) {
    const float* x  = (const float*)d_in[0];
    const int*   ei = (const int*)d_in[1];
    const int*   et = (const int*)d_in[2];
    const float* W1 = (const float*)d_in[3];
    const float* r1 = (const float*)d_in[4];
    const float* b1 = (const float*)d_in[5];
    const float* W2 = (const float*)d_in[6];
    const float* r2 = (const float*)d_in[7];
    const float* b2 = (const float*)d_in[8];
    const float* Wc = (const float*)d_in[9];
    const float* bc = (const float*)d_in[10];

    int M = in_sizes[0] / HD;    // 50000
    int E = in_sizes[1] / 2;     // 500000
    const int* src = ei;
    const int* dst = ei + E;

    float *agg, *h1, *h2;
    int *cnt, *off, *cur, *bsum, *esrc;
    __nv_bfloat16 *Bh1, *Bl1, *Bh2, *Bl2;
    cudaGetSymbolAddress((void**)&agg, g_agg);
    cudaGetSymbolAddress((void**)&cnt, g_cnt);
    cudaGetSymbolAddress((void**)&off, g_off);
    cudaGetSymbolAddress((void**)&cur, g_cur);
    cudaGetSymbolAddress((void**)&bsum, g_bsum);
    cudaGetSymbolAddress((void**)&esrc, g_esrc);
    cudaGetSymbolAddress((void**)&h1, g_h1);
    cudaGetSymbolAddress((void**)&h2, g_h2);
    cudaGetSymbolAddress((void**)&Bh1, g_Bh1);
    cudaGetSymbolAddress((void**)&Bl1, g_Bl1);
    cudaGetSymbolAddress((void**)&Bh2, g_Bh2);
    cudaGetSymbolAddress((void**)&Bl2, g_Bl2);

    int nk = M * RR;
    int nb = (nk + 1023) / 1024;
    int mblocks = (M + 127) / 128;
    int eblocks = (E + 255) / 256;
    int pblocks = (128 * KTOT + 255) / 256;
    int ablocks = (M * 32 + 255) / 256;

    // weight prep (static per call)
    prep_kernel<<<pblocks, 256>>>(r1, W1, Bh1, Bl1);
    prep_kernel<<<pblocks, 256>>>(r2, W2, Bh2, Bl2);

    // ---- CSR build (shared by both layers) ----
    cudaMemsetAsync(cnt, 0, nk * sizeof(int));
    count_kernel<<<eblocks, 256>>>(dst, et, cnt, E);
    scan1_kernel<<<nb, 256>>>(cnt, bsum, nk);
    scan2_kernel<<<1, 512>>>(bsum, nb);
    scan3_kernel<<<nb, 256>>>(cnt, bsum, off, cur, nk);
    place_kernel<<<eblocks, 256>>>(src, dst, et, cur, esrc, E);

    // ---- layer 1 ----
    agg_kernel<<<ablocks, 256>>>(x, esrc, off, cur, agg, M);
    rgcn_mma<<<mblocks, 256>>>(x, agg, cnt, Bh1, Bl1, b1, h1, M);

    // ---- layer 2 ----
    agg_kernel<<<ablocks, 256>>>(h1, esrc, off, cur, agg, M);
    rgcn_mma<<<mblocks, 256>>>(h1, agg, cnt, Bh2, Bl2, b2, h2, M);

    // ---- classifier ----
    classify_kernel<<<((M * 32) + 255) / 256, 256>>>(h2, Wc, bc, (float*)d_out, M);
}